// round 1
// baseline (speedup 1.0000x reference)
#include <cuda_runtime.h>
#include <cstdint>

#define B_  2
#define N_  512
#define C_  128
#define H_  8
#define CD_ 16

// ---------------- scratch (device globals: no allocations allowed) ----------
__device__ float g_Q[B_ * N_ * C_];              // pre-scaled by 1/sqrt(CD)=0.25
__device__ float g_K[B_ * N_ * C_];
__device__ float g_V[B_ * N_ * C_];
__device__ float g_S[B_ * H_ * N_ * N_];         // stored TRANSPOSED: [b,h,j,i]

// ---------------- packed f32x2 helpers --------------------------------------
__device__ __forceinline__ void fma2(unsigned long long& acc,
                                     unsigned long long a,
                                     unsigned long long b) {
    asm("fma.rn.f32x2 %0, %1, %2, %0;" : "+l"(acc) : "l"(a), "l"(b));
}
__device__ __forceinline__ unsigned long long pack2(float lo, float hi) {
    unsigned long long r;
    asm("mov.b64 %0, {%1, %2};" : "=l"(r) : "f"(lo), "f"(hi));
    return r;
}
__device__ __forceinline__ float2 unpack2(unsigned long long v) {
    float2 f;
    asm("mov.b64 {%0, %1}, %2;" : "=f"(f.x), "=f"(f.y) : "l"(v));
    return f;
}

// ============================================================================
// Kernel 1: Q/K/V projections.  Q gets the 1/sqrt(CD) factor folded in.
// 98304 threads, each produces 4 outputs of one of {Q,K,V}.
// ============================================================================
__global__ void qkv_kernel(const float* __restrict__ h,
                           const float* __restrict__ Wq,
                           const float* __restrict__ Wk,
                           const float* __restrict__ Wv) {
    int gid = blockIdx.x * blockDim.x + threadIdx.x;   // [0, 98304)
    int row = gid / 96;                                // b*N + n
    int q   = gid % 96;
    int mat = q >> 5;                                  // 0:Q 1:K 2:V
    int d   = (q & 31) * 4;

    const float* W   = (mat == 0) ? Wq : (mat == 1) ? Wk : Wv;
    float*       out = (mat == 0) ? g_Q : (mat == 1) ? g_K : g_V;
    const float* hrow = h + (size_t)row * C_;

    float4 acc = make_float4(0.f, 0.f, 0.f, 0.f);
#pragma unroll 4
    for (int c = 0; c < C_; c++) {
        float  hv = __ldg(hrow + c);
        float4 w  = *(const float4*)(W + (size_t)c * C_ + d);
        acc.x += hv * w.x; acc.y += hv * w.y;
        acc.z += hv * w.z; acc.w += hv * w.w;
    }
    if (mat == 0) { acc.x *= 0.25f; acc.y *= 0.25f; acc.z *= 0.25f; acc.w *= 0.25f; }
    *(float4*)(out + (size_t)row * C_ + d) = acc;
}

// ============================================================================
// Kernel 2 (the big one): Pe = e @ We fused with edge gating, e_out store,
// per-head channel reduction, clamp, transposed s store.
//
// Persistent CTAs. CTA = 256 threads (8 warps), 2 CTAs/SM (96 KB smem).
// Each chunk = 64 consecutive rows sharing (b,i); warp handles 8 rows (8 j's).
// Inner product uses packed fma.rn.f32x2; thread owns channels d=4*lane..+3.
// e tile staged TRANSPOSED ([c][r], 8 rows) with a conflict-free STS mapping.
// ============================================================================
__global__ void __launch_bounds__(256, 2)
edge_kernel(const float* __restrict__ e,
            const float* __restrict__ We,
            float* __restrict__ out_e) {
    extern __shared__ float smem[];
    float* sW = smem;                                   // 128*128 = 64 KB
    const int tid  = threadIdx.x;
    const int warp = tid >> 5;
    const int lane = tid & 31;
    float* sE = smem + C_ * C_ + warp * (C_ * 8);       // per-warp [c][r] tile

    // load We once per CTA
    for (int idx = tid; idx < C_ * C_ / 4; idx += 256)
        ((float4*)sW)[idx] = ((const float4*)We)[idx];
    __syncthreads();

    const int NCHUNK = B_ * N_ * N_ / 64;               // 8192
    const int r_mine = (lane >> 2) & 7;                 // row this lane stages
    const int c_off  = lane & 3;                        // c residue this lane stages

    for (int cid = blockIdx.x; cid < NCHUNK; cid += gridDim.x) {
        int bi = cid >> 3;                              // b*N + i
        int b  = bi >> 9;
        int i  = bi & (N_ - 1);
        int j0 = (cid & 7) << 6;
        int jw = j0 + warp * 8;

        // ---- stage 8 e rows transposed into sE[c*8 + r]  (conflict-free STS)
        {
            const float* erow = e + ((size_t)bi * N_ + jw + r_mine) * C_;
#pragma unroll 8
            for (int m = 0; m < 32; m++) {
                int c = 4 * m + c_off;
                sE[c * 8 + r_mine] = __ldg(erow + c);
            }
        }
        __syncwarp();

        // ---- main GEMM micro-kernel: acc[p][d] = f32x2 over rows (2p,2p+1)
        unsigned long long acc[4][4];
#pragma unroll
        for (int p = 0; p < 4; p++)
#pragma unroll
            for (int k = 0; k < 4; k++) acc[p][k] = 0ull;

        const float* sWl = sW + 4 * lane;
#pragma unroll 4
        for (int c = 0; c < C_; c++) {
            float4 w4 = *(const float4*)(sWl + c * C_);
            unsigned long long ws0 = pack2(w4.x, w4.x);
            unsigned long long ws1 = pack2(w4.y, w4.y);
            unsigned long long ws2 = pack2(w4.z, w4.z);
            unsigned long long ws3 = pack2(w4.w, w4.w);
            double2 ea = *(const double2*)(sE + c * 8);      // rows (0,1),(2,3)
            double2 eb = *(const double2*)(sE + c * 8 + 4);  // rows (4,5),(6,7)
            unsigned long long e01 = __double_as_longlong(ea.x);
            unsigned long long e23 = __double_as_longlong(ea.y);
            unsigned long long e45 = __double_as_longlong(eb.x);
            unsigned long long e67 = __double_as_longlong(eb.y);
            fma2(acc[0][0], e01, ws0); fma2(acc[0][1], e01, ws1);
            fma2(acc[0][2], e01, ws2); fma2(acc[0][3], e01, ws3);
            fma2(acc[1][0], e23, ws0); fma2(acc[1][1], e23, ws1);
            fma2(acc[1][2], e23, ws2); fma2(acc[1][3], e23, ws3);
            fma2(acc[2][0], e45, ws0); fma2(acc[2][1], e45, ws1);
            fma2(acc[2][2], e45, ws2); fma2(acc[2][3], e45, ws3);
            fma2(acc[3][0], e67, ws0); fma2(acc[3][1], e67, ws1);
            fma2(acc[3][2], e67, ws2); fma2(acc[3][3], e67, ws3);
        }
        __syncwarp();   // protect sE before next chunk overwrites it

        // ---- epilogue: gate by Q_i * K_j, store e_out, head-sum -> clamped s
        float4 q4 = *(const float4*)(g_Q + (size_t)bi * C_ + 4 * lane);
        int head = lane >> 2;
#pragma unroll
        for (int p = 0; p < 4; p++) {
            float2 a0 = unpack2(acc[p][0]);
            float2 a1 = unpack2(acc[p][1]);
            float2 a2 = unpack2(acc[p][2]);
            float2 a3 = unpack2(acc[p][3]);
#pragma unroll
            for (int sub = 0; sub < 2; sub++) {
                int j = jw + 2 * p + sub;
                float4 k4 = *(const float4*)(g_K + ((size_t)b * N_ + j) * C_ + 4 * lane);
                float4 eo;
                eo.x = (sub ? a0.y : a0.x) * q4.x * k4.x;
                eo.y = (sub ? a1.y : a1.x) * q4.y * k4.y;
                eo.z = (sub ? a2.y : a2.x) * q4.z * k4.z;
                eo.w = (sub ? a3.y : a3.x) * q4.w * k4.w;
                *(float4*)(out_e + ((size_t)bi * N_ + j) * C_ + 4 * lane) = eo;

                float hs = eo.x + eo.y + eo.z + eo.w;
                hs += __shfl_xor_sync(0xffffffffu, hs, 1);
                hs += __shfl_xor_sync(0xffffffffu, hs, 2);
                if ((lane & 3) == 0) {
                    hs = fminf(fmaxf(hs, -5.f), 5.f);
                    g_S[((size_t)(b * H_ + head) * N_ + j) * N_ + i] = hs;
                }
            }
        }
    }
}

// ============================================================================
// Kernel 3: softmax over the QUERY axis i.  g_S rows are [b,h,j][i] contiguous.
// One block per (b,h,j) row of 512 elements. Values pre-clamped to [-5,5], so
// no max-subtraction needed.
// ============================================================================
__global__ void softmax_kernel() {
    float* row = g_S + (size_t)blockIdx.x * N_;
    int tid = threadIdx.x;                       // 128 threads, 4 elems each
    float4 v = ((float4*)row)[tid];
    v.x = __expf(v.x); v.y = __expf(v.y); v.z = __expf(v.z); v.w = __expf(v.w);
    float s = v.x + v.y + v.z + v.w;
#pragma unroll
    for (int o = 16; o; o >>= 1) s += __shfl_xor_sync(0xffffffffu, s, o);
    __shared__ float ws[4];
    if ((tid & 31) == 0) ws[tid >> 5] = s;
    __syncthreads();
    float inv = 1.f / (ws[0] + ws[1] + ws[2] + ws[3]);
    v.x *= inv; v.y *= inv; v.z *= inv; v.w *= inv;
    ((float4*)row)[tid] = v;
}

// ============================================================================
// Kernel 4: h_out[b,i,h*16+c] = sum_j attn_T[b,h,j,i] * V[b,j,h*16+c]
// CTA = (b,h,i-tile of 64). 256 threads: lane-contiguous i for coalesced attn.
// ============================================================================
__global__ void hout_kernel(float* __restrict__ out_h) {
    int cta  = blockIdx.x;                       // 128 = 16 (b,h) * 8 i-tiles
    int bh   = cta >> 3;
    int b    = bh >> 3;
    int head = bh & 7;
    int i0   = (cta & 7) << 6;
    int t    = threadIdx.x;
    int ii   = t & 63;
    int cg   = t >> 6;                           // 0..3 -> channels cg*4..+3

    const float* arow = g_S + (size_t)bh * N_ * N_;
    const float* vcol = g_V + (size_t)b * N_ * C_ + head * CD_ + cg * 4;
    int i = i0 + ii;

    float4 acc = make_float4(0.f, 0.f, 0.f, 0.f);
#pragma unroll 4
    for (int j = 0; j < N_; j++) {
        float  a  = __ldg(arow + (size_t)j * N_ + i);
        float4 v4 = *(const float4*)(vcol + (size_t)j * C_);
        acc.x += a * v4.x; acc.y += a * v4.y;
        acc.z += a * v4.z; acc.w += a * v4.w;
    }
    *(float4*)(out_h + ((size_t)(b * N_ + i)) * C_ + head * CD_ + cg * 4) = acc;
}

// ============================================================================
extern "C" void kernel_launch(void* const* d_in, const int* in_sizes, int n_in,
                              void* d_out, int out_size) {
    const float* h  = (const float*)d_in[0];
    const float* e  = (const float*)d_in[1];
    const float* Wq = (const float*)d_in[2];
    const float* Wk = (const float*)d_in[3];
    const float* Wv = (const float*)d_in[4];
    const float* We = (const float*)d_in[5];

    float* out_h = (float*)d_out;                       // [B,N,C]
    float* out_e = (float*)d_out + B_ * N_ * C_;        // [B,N,N,C]

    // 96 KB dynamic smem for the edge kernel (idempotent; safe under capture)
    cudaFuncSetAttribute(edge_kernel,
                         cudaFuncAttributeMaxDynamicSharedMemorySize, 96 * 1024);

    qkv_kernel<<<384, 256>>>(h, Wq, Wk, Wv);
    edge_kernel<<<304, 256, 96 * 1024>>>(e, We, out_e);
    softmax_kernel<<<B_ * H_ * N_, 128>>>();
    hout_kernel<<<128, 256>>>(out_h);
}

// round 2
// speedup vs baseline: 1.0086x; 1.0086x over previous
#include <cuda_runtime.h>
#include <cstdint>

#define B_  2
#define N_  512
#define C_  128
#define H_  8
#define CD_ 16

// ---------------- scratch (device globals: no allocations allowed) ----------
__device__ float g_Q[B_ * N_ * C_];              // pre-scaled by 1/sqrt(CD)=0.25
__device__ float g_K[B_ * N_ * C_];
__device__ float g_V[B_ * N_ * C_];
__device__ float g_S[B_ * H_ * N_ * N_];         // stored TRANSPOSED: [b,h,j,i]

// ---------------- packed f32x2 helpers --------------------------------------
__device__ __forceinline__ void fma2(unsigned long long& acc,
                                     unsigned long long a,
                                     unsigned long long b) {
    asm("fma.rn.f32x2 %0, %1, %2, %0;" : "+l"(acc) : "l"(a), "l"(b));
}
__device__ __forceinline__ unsigned long long pack2(float lo, float hi) {
    unsigned long long r;
    asm("mov.b64 %0, {%1, %2};" : "=l"(r) : "f"(lo), "f"(hi));
    return r;
}
__device__ __forceinline__ float2 unpack2(unsigned long long v) {
    float2 f;
    asm("mov.b64 {%0, %1}, %2;" : "=f"(f.x), "=f"(f.y) : "l"(v));
    return f;
}

// ============================================================================
// Kernel 1: Q/K/V projections.  Q gets the 1/sqrt(CD) factor folded in.
// 98304 threads, each produces 4 outputs of one of {Q,K,V}.
// ============================================================================
__global__ void qkv_kernel(const float* __restrict__ h,
                           const float* __restrict__ Wq,
                           const float* __restrict__ Wk,
                           const float* __restrict__ Wv) {
    int gid = blockIdx.x * blockDim.x + threadIdx.x;   // [0, 98304)
    int row = gid / 96;                                // b*N + n
    int q   = gid % 96;
    int mat = q >> 5;                                  // 0:Q 1:K 2:V
    int d   = (q & 31) * 4;

    const float* W   = (mat == 0) ? Wq : (mat == 1) ? Wk : Wv;
    float*       out = (mat == 0) ? g_Q : (mat == 1) ? g_K : g_V;
    const float* hrow = h + (size_t)row * C_;

    float4 acc = make_float4(0.f, 0.f, 0.f, 0.f);
#pragma unroll 4
    for (int c = 0; c < C_; c++) {
        float  hv = __ldg(hrow + c);
        float4 w  = *(const float4*)(W + (size_t)c * C_ + d);
        acc.x += hv * w.x; acc.y += hv * w.y;
        acc.z += hv * w.z; acc.w += hv * w.w;
    }
    if (mat == 0) { acc.x *= 0.25f; acc.y *= 0.25f; acc.z *= 0.25f; acc.w *= 0.25f; }
    *(float4*)(out + (size_t)row * C_ + d) = acc;
}

// ============================================================================
// Kernel 2 (the big one): Pe = e @ We fused with edge gating, e_out store,
// per-head channel reduction, clamp, transposed s store.
//
// Persistent CTAs. CTA = 256 threads (8 warps), 2 CTAs/SM (96 KB smem).
// Each chunk = 64 consecutive rows sharing (b,i); warp handles 8 rows (8 j's).
// Inner product uses packed fma.rn.f32x2; thread owns channels d=4*lane..+3.
// e tile staged TRANSPOSED ([c][r], 8 rows) with a conflict-free STS mapping.
// ============================================================================
__global__ void __launch_bounds__(256, 2)
edge_kernel(const float* __restrict__ e,
            const float* __restrict__ We,
            float* __restrict__ out_e) {
    extern __shared__ float smem[];
    float* sW = smem;                                   // 128*128 = 64 KB
    const int tid  = threadIdx.x;
    const int warp = tid >> 5;
    const int lane = tid & 31;
    float* sE = smem + C_ * C_ + warp * (C_ * 8);       // per-warp [c][r] tile

    // load We once per CTA
    for (int idx = tid; idx < C_ * C_ / 4; idx += 256)
        ((float4*)sW)[idx] = ((const float4*)We)[idx];
    __syncthreads();

    const int NCHUNK = B_ * N_ * N_ / 64;               // 8192
    const int r_mine = (lane >> 2) & 7;                 // row this lane stages
    const int c_off  = lane & 3;                        // c residue this lane stages

    for (int cid = blockIdx.x; cid < NCHUNK; cid += gridDim.x) {
        int bi = cid >> 3;                              // b*N + i
        int b  = bi >> 9;
        int i  = bi & (N_ - 1);
        int j0 = (cid & 7) << 6;
        int jw = j0 + warp * 8;

        // ---- stage 8 e rows transposed into sE[c*8 + r]  (conflict-free STS)
        {
            const float* erow = e + ((size_t)bi * N_ + jw + r_mine) * C_;
#pragma unroll 8
            for (int m = 0; m < 32; m++) {
                int c = 4 * m + c_off;
                sE[c * 8 + r_mine] = __ldg(erow + c);
            }
        }
        __syncwarp();

        // ---- main GEMM micro-kernel: acc[p][d] = f32x2 over rows (2p,2p+1)
        unsigned long long acc[4][4];
#pragma unroll
        for (int p = 0; p < 4; p++)
#pragma unroll
            for (int k = 0; k < 4; k++) acc[p][k] = 0ull;

        const float* sWl = sW + 4 * lane;
#pragma unroll 4
        for (int c = 0; c < C_; c++) {
            float4 w4 = *(const float4*)(sWl + c * C_);
            unsigned long long ws0 = pack2(w4.x, w4.x);
            unsigned long long ws1 = pack2(w4.y, w4.y);
            unsigned long long ws2 = pack2(w4.z, w4.z);
            unsigned long long ws3 = pack2(w4.w, w4.w);
            double2 ea = *(const double2*)(sE + c * 8);      // rows (0,1),(2,3)
            double2 eb = *(const double2*)(sE + c * 8 + 4);  // rows (4,5),(6,7)
            unsigned long long e01 = __double_as_longlong(ea.x);
            unsigned long long e23 = __double_as_longlong(ea.y);
            unsigned long long e45 = __double_as_longlong(eb.x);
            unsigned long long e67 = __double_as_longlong(eb.y);
            fma2(acc[0][0], e01, ws0); fma2(acc[0][1], e01, ws1);
            fma2(acc[0][2], e01, ws2); fma2(acc[0][3], e01, ws3);
            fma2(acc[1][0], e23, ws0); fma2(acc[1][1], e23, ws1);
            fma2(acc[1][2], e23, ws2); fma2(acc[1][3], e23, ws3);
            fma2(acc[2][0], e45, ws0); fma2(acc[2][1], e45, ws1);
            fma2(acc[2][2], e45, ws2); fma2(acc[2][3], e45, ws3);
            fma2(acc[3][0], e67, ws0); fma2(acc[3][1], e67, ws1);
            fma2(acc[3][2], e67, ws2); fma2(acc[3][3], e67, ws3);
        }
        __syncwarp();   // protect sE before next chunk overwrites it

        // ---- epilogue: gate by Q_i * K_j, store e_out, head-sum -> clamped s
        float4 q4 = *(const float4*)(g_Q + (size_t)bi * C_ + 4 * lane);
        int head = lane >> 2;
#pragma unroll
        for (int p = 0; p < 4; p++) {
            float2 a0 = unpack2(acc[p][0]);
            float2 a1 = unpack2(acc[p][1]);
            float2 a2 = unpack2(acc[p][2]);
            float2 a3 = unpack2(acc[p][3]);
#pragma unroll
            for (int sub = 0; sub < 2; sub++) {
                int j = jw + 2 * p + sub;
                float4 k4 = *(const float4*)(g_K + ((size_t)b * N_ + j) * C_ + 4 * lane);
                float4 eo;
                eo.x = (sub ? a0.y : a0.x) * q4.x * k4.x;
                eo.y = (sub ? a1.y : a1.x) * q4.y * k4.y;
                eo.z = (sub ? a2.y : a2.x) * q4.z * k4.z;
                eo.w = (sub ? a3.y : a3.x) * q4.w * k4.w;
                *(float4*)(out_e + ((size_t)bi * N_ + j) * C_ + 4 * lane) = eo;

                float hs = eo.x + eo.y + eo.z + eo.w;
                hs += __shfl_xor_sync(0xffffffffu, hs, 1);
                hs += __shfl_xor_sync(0xffffffffu, hs, 2);
                if ((lane & 3) == 0) {
                    hs = fminf(fmaxf(hs, -5.f), 5.f);
                    g_S[((size_t)(b * H_ + head) * N_ + j) * N_ + i] = hs;
                }
            }
        }
    }
}

// ============================================================================
// Kernel 3: softmax over the QUERY axis i.  g_S rows are [b,h,j][i] contiguous.
// One block per (b,h,j) row of 512 elements. Values pre-clamped to [-5,5], so
// no max-subtraction needed.
// ============================================================================
__global__ void softmax_kernel() {
    float* row = g_S + (size_t)blockIdx.x * N_;
    int tid = threadIdx.x;                       // 128 threads, 4 elems each
    float4 v = ((float4*)row)[tid];
    v.x = __expf(v.x); v.y = __expf(v.y); v.z = __expf(v.z); v.w = __expf(v.w);
    float s = v.x + v.y + v.z + v.w;
#pragma unroll
    for (int o = 16; o; o >>= 1) s += __shfl_xor_sync(0xffffffffu, s, o);
    __shared__ float ws[4];
    if ((tid & 31) == 0) ws[tid >> 5] = s;
    __syncthreads();
    float inv = 1.f / (ws[0] + ws[1] + ws[2] + ws[3]);
    v.x *= inv; v.y *= inv; v.z *= inv; v.w *= inv;
    ((float4*)row)[tid] = v;
}

// ============================================================================
// Kernel 4: h_out[b,i,h*16+c] = sum_j attn_T[b,h,j,i] * V[b,j,h*16+c]
// CTA = (b,h,i-tile of 64). 256 threads: lane-contiguous i for coalesced attn.
// ============================================================================
__global__ void hout_kernel(float* __restrict__ out_h) {
    int cta  = blockIdx.x;                       // 128 = 16 (b,h) * 8 i-tiles
    int bh   = cta >> 3;
    int b    = bh >> 3;
    int head = bh & 7;
    int i0   = (cta & 7) << 6;
    int t    = threadIdx.x;
    int ii   = t & 63;
    int cg   = t >> 6;                           // 0..3 -> channels cg*4..+3

    const float* arow = g_S + (size_t)bh * N_ * N_;
    const float* vcol = g_V + (size_t)b * N_ * C_ + head * CD_ + cg * 4;
    int i = i0 + ii;

    float4 acc = make_float4(0.f, 0.f, 0.f, 0.f);
#pragma unroll 4
    for (int j = 0; j < N_; j++) {
        float  a  = __ldg(arow + (size_t)j * N_ + i);
        float4 v4 = *(const float4*)(vcol + (size_t)j * C_);
        acc.x += a * v4.x; acc.y += a * v4.y;
        acc.z += a * v4.z; acc.w += a * v4.w;
    }
    *(float4*)(out_h + ((size_t)(b * N_ + i)) * C_ + head * CD_ + cg * 4) = acc;
}

// ============================================================================
extern "C" void kernel_launch(void* const* d_in, const int* in_sizes, int n_in,
                              void* d_out, int out_size) {
    const float* h  = (const float*)d_in[0];
    const float* e  = (const float*)d_in[1];
    const float* Wq = (const float*)d_in[2];
    const float* Wk = (const float*)d_in[3];
    const float* Wv = (const float*)d_in[4];
    const float* We = (const float*)d_in[5];

    float* out_h = (float*)d_out;                       // [B,N,C]
    float* out_e = (float*)d_out + B_ * N_ * C_;        // [B,N,N,C]

    // 96 KB dynamic smem for the edge kernel (idempotent; safe under capture)
    cudaFuncSetAttribute(edge_kernel,
                         cudaFuncAttributeMaxDynamicSharedMemorySize, 96 * 1024);

    qkv_kernel<<<384, 256>>>(h, Wq, Wk, Wv);
    edge_kernel<<<304, 256, 96 * 1024>>>(e, We, out_e);
    softmax_kernel<<<B_ * H_ * N_, 128>>>();
    hout_kernel<<<128, 256>>>(out_h);
}